// round 5
// baseline (speedup 1.0000x reference)
#include <cuda_runtime.h>
#include <cstdint>

#define BSZ 4
#define LM  256
#define LE  512
#define HD  512
#define VOC 32000

// Scratch (device globals; no allocation allowed in kernel_launch)
__device__ float g_G[HD * HD];            // W_m @ W_e^T * H^-0.5   (1 MB)
__device__ float g_T[BSZ * LM * HD];      // M @ G                  (2 MB)
__device__ float g_logits[BSZ * LM * LE]; // T @ E^T                (2 MB)
__device__ float g_lam[BSZ * LM];

// ---------------------------------------------------------------------------
// Zero the whole output (131 MB). Pure DRAM-store kernel; runs on the side
// stream concurrently with the GEMM chain.
// ---------------------------------------------------------------------------
__global__ __launch_bounds__(256) void k_zero(float4* __restrict__ p, long n4)
{
    long i = (long)blockIdx.x * blockDim.x + threadIdx.x;
    long s = (long)gridDim.x * blockDim.x;
    float4 z = make_float4(0.f, 0.f, 0.f, 0.f);
    for (; i < n4; i += s) p[i] = z;
}

// ---------------------------------------------------------------------------
// lambda = sigmoid(concat(D, Cq, Cc) @ W_lambda + b_lambda), one block per row
// ---------------------------------------------------------------------------
__global__ __launch_bounds__(256) void k_lambda(
    const float* __restrict__ D, const float* __restrict__ Cq,
    const float* __restrict__ Cc, const float* __restrict__ Wl,
    const float* __restrict__ bl)
{
    int r = blockIdx.x;
    int t = threadIdx.x;
    const float* d  = D  + (long)r * HD;
    const float* cq = Cq + (long)r * HD;
    const float* cc = Cc + (long)r * HD;
    float s = 0.f;
    for (int j = t; j < HD; j += 256)
        s += d[j] * Wl[j] + cq[j] * Wl[HD + j] + cc[j] * Wl[2 * HD + j];
    __shared__ float red[256];
    red[t] = s; __syncthreads();
    for (int o = 128; o > 0; o >>= 1) {
        if (t < o) red[t] += red[t + o];
        __syncthreads();
    }
    if (t == 0) {
        float x = red[0] + bl[0];
        g_lam[r] = 1.f / (1.f + __expf(-x));
    }
}

// ---------------------------------------------------------------------------
// tf32 tensor-core GEMM: 64x64 block tile, 256 threads (4x2 warps, 16x32
// warp tiles -> 2 warps per SMSP), BK=32, cp.async double-buffered smem,
// mma.sync.m16n8k8.tf32.
// TB=true:  C[m,n] = alpha * sum_k A[m,k] * B[n,k]   (NT, both K-major)
// TB=false: C[m,n] = alpha * sum_k A[m,k] * B[k,n]   (NN)
// K fixed = 512. Batched via blockIdx.z.
// ---------------------------------------------------------------------------
__device__ __forceinline__ void cp16(void* dst, const void* src)
{
    uint32_t d = (uint32_t)__cvta_generic_to_shared(dst);
    asm volatile("cp.async.cg.shared.global [%0], [%1], 16;\n"
                 :: "r"(d), "l"(src));
}
__device__ __forceinline__ void cp_commit()
{
    asm volatile("cp.async.commit_group;\n" ::: "memory");
}
__device__ __forceinline__ void cp_wait0()
{
    asm volatile("cp.async.wait_group 0;\n" ::: "memory");
}
__device__ __forceinline__ void mma_tf32(float* d, const uint32_t* a,
                                         const uint32_t* b)
{
    asm volatile(
        "mma.sync.aligned.m16n8k8.row.col.f32.tf32.tf32.f32 "
        "{%0,%1,%2,%3}, {%4,%5,%6,%7}, {%8,%9}, {%0,%1,%2,%3};\n"
        : "+f"(d[0]), "+f"(d[1]), "+f"(d[2]), "+f"(d[3])
        : "r"(a[0]), "r"(a[1]), "r"(a[2]), "r"(a[3]),
          "r"(b[0]), "r"(b[1]));
}

#define PA 36   // smem pitch for K-major tiles (banks: 4*gid+tig, conflict-free)
#define PB 72   // smem pitch for NN B tile    (banks: 8*tig+gid, conflict-free)

template <bool TB>
__global__ __launch_bounds__(256) void k_gemm_tc(
    const float* __restrict__ A, const float* __restrict__ B,
    float* __restrict__ C, int lda, int ldb, int ldc,
    long strA, long strB, long strC, float alpha)
{
    __shared__ float As[2][64 * PA];
    __shared__ float Bs[2][2304];   // NT: 64*PA, NN: 32*PB (both 2304 floats)

    long bz = blockIdx.z;
    A += bz * strA; B += bz * strB; C += bz * strC;
    const int m0 = blockIdx.y * 64, n0 = blockIdx.x * 64;

    const int tid  = threadIdx.x;
    const int lane = tid & 31, w = tid >> 5;
    const int gid = lane >> 2, tig = lane & 3;
    const int wm = (w & 3) * 16, wn = (w >> 2) * 32;

    const int NK = HD / 32;  // 16 mainloop iters

    // tile loaders: 512 16B chunks per tile, 2 per thread
    auto loadA = [&](int buf, int kt) {
        int k0 = kt * 32;
#pragma unroll
        for (int i = 0; i < 2; i++) {
            int id = tid + i * 256;
            int row = id >> 3, cc = id & 7;
            cp16(&As[buf][row * PA + cc * 4],
                 A + (long)(m0 + row) * lda + k0 + cc * 4);
        }
    };
    auto loadB = [&](int buf, int kt) {
        int k0 = kt * 32;
        if (TB) {
#pragma unroll
            for (int i = 0; i < 2; i++) {
                int id = tid + i * 256;
                int row = id >> 3, cc = id & 7;
                cp16(&Bs[buf][row * PA + cc * 4],
                     B + (long)(n0 + row) * ldb + k0 + cc * 4);
            }
        } else {
#pragma unroll
            for (int i = 0; i < 2; i++) {
                int id = tid + i * 256;
                int row = id >> 4, cc = id & 15;
                cp16(&Bs[buf][row * PB + cc * 4],
                     B + (long)(k0 + row) * ldb + n0 + cc * 4);
            }
        }
    };

    float acc[4][4] = {};   // [nj][frag]

    loadA(0, 0); loadB(0, 0); cp_commit();
    cp_wait0(); __syncthreads();

    int buf = 0;
    for (int kt = 0; kt < NK; kt++) {
        if (kt + 1 < NK) {
            loadA(buf ^ 1, kt + 1);
            loadB(buf ^ 1, kt + 1);
            cp_commit();
        }
#pragma unroll
        for (int ks = 0; ks < 4; ks++) {
            const int kk = ks * 8;
            uint32_t a[4];
            {
                int rb = wm + gid;
                a[0] = __float_as_uint(As[buf][(rb)     * PA + kk + tig]);
                a[1] = __float_as_uint(As[buf][(rb + 8) * PA + kk + tig]);
                a[2] = __float_as_uint(As[buf][(rb)     * PA + kk + tig + 4]);
                a[3] = __float_as_uint(As[buf][(rb + 8) * PA + kk + tig + 4]);
            }
            uint32_t b[4][2];
#pragma unroll
            for (int nj = 0; nj < 4; nj++) {
                int cb = wn + nj * 8 + gid;
                if (TB) {
                    b[nj][0] = __float_as_uint(Bs[buf][cb * PA + kk + tig]);
                    b[nj][1] = __float_as_uint(Bs[buf][cb * PA + kk + tig + 4]);
                } else {
                    b[nj][0] = __float_as_uint(Bs[buf][(kk + tig)     * PB + cb]);
                    b[nj][1] = __float_as_uint(Bs[buf][(kk + tig + 4) * PB + cb]);
                }
            }
#pragma unroll
            for (int nj = 0; nj < 4; nj++)
                mma_tf32(acc[nj], a, b[nj]);
        }
        if (kt + 1 < NK) {
            cp_wait0(); __syncthreads();
            buf ^= 1;
        }
    }

#pragma unroll
    for (int nj = 0; nj < 4; nj++) {
        int r0 = m0 + wm + gid;
        int c0 = n0 + wn + nj * 8 + 2 * tig;
        C[(long)r0 * ldc + c0]           = acc[nj][0] * alpha;
        C[(long)r0 * ldc + c0 + 1]       = acc[nj][1] * alpha;
        C[(long)(r0 + 8) * ldc + c0]     = acc[nj][2] * alpha;
        C[(long)(r0 + 8) * ldc + c0 + 1] = acc[nj][3] * alpha;
    }
}

// ---------------------------------------------------------------------------
// One block per (b,m) row: dual softmax over the shared logits row (with the
// two bias vectors), combine with lambda, scatter-add at inputs[b,e].
// Output rows are pre-zeroed by k_zero (ordered via the graph join).
// ---------------------------------------------------------------------------
__global__ __launch_bounds__(256) void k_scatter(
    const int* __restrict__ idx, const float* __restrict__ bq,
    const float* __restrict__ bc, float* __restrict__ out)
{
    int r = blockIdx.x;
    int b = r / LM;
    int t = threadIdx.x;

    float* orow = out + (long)r * VOC;
    const float* lr = g_logits + (long)r * LE;
    float lam = g_lam[r];

    float vq[2], vc[2];
#pragma unroll
    for (int i = 0; i < 2; i++) {
        int e = t + i * 256;
        float l = lr[e];
        vq[i] = l + bq[b * LE + e];
        vc[i] = l + bc[b * LE + e];
    }

    __shared__ float red[256];
    red[t] = fmaxf(vq[0], vq[1]); __syncthreads();
    for (int o = 128; o > 0; o >>= 1) {
        if (t < o) red[t] = fmaxf(red[t], red[t + o]);
        __syncthreads();
    }
    float mq = red[0]; __syncthreads();
    red[t] = fmaxf(vc[0], vc[1]); __syncthreads();
    for (int o = 128; o > 0; o >>= 1) {
        if (t < o) red[t] = fmaxf(red[t], red[t + o]);
        __syncthreads();
    }
    float mc = red[0]; __syncthreads();

    float eq[2], ec[2], sq = 0.f, sc = 0.f;
#pragma unroll
    for (int i = 0; i < 2; i++) {
        eq[i] = __expf(vq[i] - mq); sq += eq[i];
        ec[i] = __expf(vc[i] - mc); sc += ec[i];
    }
    red[t] = sq; __syncthreads();
    for (int o = 128; o > 0; o >>= 1) {
        if (t < o) red[t] += red[t + o];
        __syncthreads();
    }
    sq = red[0]; __syncthreads();
    red[t] = sc; __syncthreads();
    for (int o = 128; o > 0; o >>= 1) {
        if (t < o) red[t] += red[t + o];
        __syncthreads();
    }
    sc = red[0];

    float iq = lam / sq, ic = (1.f - lam) / sc;
#pragma unroll
    for (int i = 0; i < 2; i++) {
        int e = t + i * 256;
        atomicAdd(orow + idx[b * LE + e], eq[i] * iq + ec[i] * ic);
    }
}

// ---------------------------------------------------------------------------
extern "C" void kernel_launch(void* const* d_in, const int* in_sizes, int n_in,
                              void* d_out, int out_size)
{
    const int*   inputs = (const int*)  d_in[0];
    const float* D      = (const float*)d_in[1];
    const float* Cq     = (const float*)d_in[2];
    const float* Cc     = (const float*)d_in[3];
    const float* Mi     = (const float*)d_in[4];
    const float* E      = (const float*)d_in[5];
    const float* bq     = (const float*)d_in[6];
    const float* bc     = (const float*)d_in[7];
    const float* Wl     = (const float*)d_in[8];
    const float* bl     = (const float*)d_in[9];
    const float* We     = (const float*)d_in[10];
    const float* Wm     = (const float*)d_in[11];
    float* out = (float*)d_out;

    float *gG, *gT, *gL;
    cudaGetSymbolAddress((void**)&gG, g_G);
    cudaGetSymbolAddress((void**)&gT, g_T);
    cudaGetSymbolAddress((void**)&gL, g_logits);

    // One-time side stream + fork/join events (resource setup only; the
    // captured work is identical on every call).
    static cudaStream_t s2 = nullptr;
    static cudaEvent_t evFork = nullptr, evJoin = nullptr;
    if (s2 == nullptr) {
        cudaStreamCreateWithFlags(&s2, cudaStreamNonBlocking);
        cudaEventCreateWithFlags(&evFork, cudaEventDisableTiming);
        cudaEventCreateWithFlags(&evJoin, cudaEventDisableTiming);
    }

    const float scale = 0.044194173824159216f;  // 512^-0.5
    const long n4 = (long)BSZ * LM * VOC / 4;   // 8,192,000 float4

    // ---- fork: side branch zeroes the output and computes lambda ----------
    cudaEventRecord(evFork, 0);
    cudaStreamWaitEvent(s2, evFork, 0);
    k_lambda<<<BSZ * LM, 256, 0, s2>>>(D, Cq, Cc, Wl, bl);
    k_zero<<<1184, 256, 0, s2>>>((float4*)out, n4);
    cudaEventRecord(evJoin, s2);

    // ---- main branch: GEMM chain ------------------------------------------
    // G = Wm @ We^T * scale      (512x512, K=512)  NT
    k_gemm_tc<true><<<dim3(8, 8, 1), 256>>>(Wm, We, gG, HD, HD, HD,
                                            0, 0, 0, scale);
    // T = M_flat @ G             (1024x512, K=512) NN
    k_gemm_tc<false><<<dim3(8, 16, 1), 256>>>(Mi, gG, gT, HD, HD, HD,
                                              0, 0, 0, 1.f);
    // logits[b] = T[b] @ E[b]^T  (256x512, K=512, batched over BS) NT
    k_gemm_tc<true><<<dim3(8, 4, BSZ), 256>>>(gT, E, gL, HD, HD, LE,
                                              (long)LM * HD, (long)LE * HD,
                                              (long)LM * LE, 1.f);

    // ---- join + scatter ----------------------------------------------------
    cudaStreamWaitEvent(0, evJoin, 0);
    k_scatter<<<BSZ * LM, 256>>>(inputs, bq, bc, out);
}

// round 6
// speedup vs baseline: 1.1464x; 1.1464x over previous
#include <cuda_runtime.h>
#include <cstdint>

#define BSZ 4
#define LM  256
#define LE  512
#define HD  512
#define VOC 32000

// Scratch (device globals; no allocation allowed in kernel_launch)
__device__ float g_Ep[BSZ * LE * HD];      // E @ We               (4 MB)
__device__ float g_Mp[BSZ * LM * HD];      // M @ Wm * scale       (2 MB)
__device__ float g_logA[BSZ * LM * LE];    // partial logits K[0:256)
__device__ float g_logB[BSZ * LM * LE];    // partial logits K[256:512)
__device__ float g_lam[BSZ * LM];

// ---------------------------------------------------------------------------
// Zero the whole output (131 MB). Capped grid (2 blocks/SM) so it saturates
// DRAM stores while leaving SM slots free for the concurrent GEMM chain.
// ---------------------------------------------------------------------------
__global__ __launch_bounds__(256) void k_zero(float4* __restrict__ p, long n4)
{
    long i = (long)blockIdx.x * blockDim.x + threadIdx.x;
    long s = (long)gridDim.x * blockDim.x;
    float4 z = make_float4(0.f, 0.f, 0.f, 0.f);
    for (; i < n4; i += s) p[i] = z;
}

// ---------------------------------------------------------------------------
// lambda = sigmoid(concat(D, Cq, Cc) @ W_lambda + b_lambda), warp per row.
// ---------------------------------------------------------------------------
__global__ __launch_bounds__(256) void k_lambda(
    const float* __restrict__ D, const float* __restrict__ Cq,
    const float* __restrict__ Cc, const float* __restrict__ Wl,
    const float* __restrict__ bl)
{
    int w = threadIdx.x >> 5, lane = threadIdx.x & 31;
    int r = blockIdx.x * 8 + w;          // 0 .. BSZ*LM-1 (grid = 128)
    const float* d  = D  + (long)r * HD;
    const float* cq = Cq + (long)r * HD;
    const float* cc = Cc + (long)r * HD;
    float s = 0.f;
    for (int j = lane; j < HD; j += 32)
        s += d[j] * Wl[j] + cq[j] * Wl[HD + j] + cc[j] * Wl[2 * HD + j];
#pragma unroll
    for (int o = 16; o > 0; o >>= 1)
        s += __shfl_xor_sync(0xffffffffu, s, o);
    if (lane == 0) {
        float x = s + bl[0];
        g_lam[r] = 1.f / (1.f + __expf(-x));
    }
}

// ---------------------------------------------------------------------------
// tf32 tensor-core GEMM core: 64x64 tile, 256 threads (4x2 warps of 16x32),
// BK=32, cp.async double-buffered smem, mma.sync.m16n8k8.tf32.
// TB=true:  C[m,n] = alpha * sum_k A[m,k] * B[n,k]   (NT, both K-major)
// TB=false: C[m,n] = alpha * sum_k A[m,k] * B[k,n]   (NN)
// ---------------------------------------------------------------------------
__device__ __forceinline__ void cp16(void* dst, const void* src)
{
    uint32_t d = (uint32_t)__cvta_generic_to_shared(dst);
    asm volatile("cp.async.cg.shared.global [%0], [%1], 16;\n"
                 :: "r"(d), "l"(src));
}
__device__ __forceinline__ void cp_commit()
{
    asm volatile("cp.async.commit_group;\n" ::: "memory");
}
__device__ __forceinline__ void cp_wait0()
{
    asm volatile("cp.async.wait_group 0;\n" ::: "memory");
}
__device__ __forceinline__ void mma_tf32(float* d, const uint32_t* a,
                                         const uint32_t* b)
{
    asm volatile(
        "mma.sync.aligned.m16n8k8.row.col.f32.tf32.tf32.f32 "
        "{%0,%1,%2,%3}, {%4,%5,%6,%7}, {%8,%9}, {%0,%1,%2,%3};\n"
        : "+f"(d[0]), "+f"(d[1]), "+f"(d[2]), "+f"(d[3])
        : "r"(a[0]), "r"(a[1]), "r"(a[2]), "r"(a[3]),
          "r"(b[0]), "r"(b[1]));
}

#define PA 36   // smem pitch, K-major tiles (banks 4*gid+tig: conflict-free)
#define PB 72   // smem pitch, NN B tile     (banks 8*tig+gid: conflict-free)

template <bool TB>
__device__ __forceinline__ void gemm_core(
    const float* __restrict__ A, const float* __restrict__ B,
    float* __restrict__ C, int lda, int ldb, int ldc,
    int m0, int n0, int kOff, int kLen, float alpha,
    float (&As)[2][64 * PA], float (&Bs)[2][2304])
{
    const int tid  = threadIdx.x;
    const int lane = tid & 31, w = tid >> 5;
    const int gid = lane >> 2, tig = lane & 3;
    const int wm = (w & 3) * 16, wn = (w >> 2) * 32;

    const int NK = kLen / 32;

    auto loadA = [&](int buf, int kt) {
        int k0 = kOff + kt * 32;
#pragma unroll
        for (int i = 0; i < 2; i++) {
            int id = tid + i * 256;
            int row = id >> 3, cc = id & 7;
            cp16(&As[buf][row * PA + cc * 4],
                 A + (long)(m0 + row) * lda + k0 + cc * 4);
        }
    };
    auto loadB = [&](int buf, int kt) {
        int k0 = kOff + kt * 32;
        if (TB) {
#pragma unroll
            for (int i = 0; i < 2; i++) {
                int id = tid + i * 256;
                int row = id >> 3, cc = id & 7;
                cp16(&Bs[buf][row * PA + cc * 4],
                     B + (long)(n0 + row) * ldb + k0 + cc * 4);
            }
        } else {
#pragma unroll
            for (int i = 0; i < 2; i++) {
                int id = tid + i * 256;
                int row = id >> 4, cc = id & 15;
                cp16(&Bs[buf][row * PB + cc * 4],
                     B + (long)(k0 + row) * ldb + n0 + cc * 4);
            }
        }
    };

    float acc[4][4] = {};

    loadA(0, 0); loadB(0, 0); cp_commit();
    cp_wait0(); __syncthreads();

    int buf = 0;
    for (int kt = 0; kt < NK; kt++) {
        if (kt + 1 < NK) {
            loadA(buf ^ 1, kt + 1);
            loadB(buf ^ 1, kt + 1);
            cp_commit();
        }
#pragma unroll
        for (int ks = 0; ks < 4; ks++) {
            const int kk = ks * 8;
            uint32_t a[4];
            {
                int rb = wm + gid;
                a[0] = __float_as_uint(As[buf][(rb)     * PA + kk + tig]);
                a[1] = __float_as_uint(As[buf][(rb + 8) * PA + kk + tig]);
                a[2] = __float_as_uint(As[buf][(rb)     * PA + kk + tig + 4]);
                a[3] = __float_as_uint(As[buf][(rb + 8) * PA + kk + tig + 4]);
            }
            uint32_t b[4][2];
#pragma unroll
            for (int nj = 0; nj < 4; nj++) {
                int cb = wn + nj * 8 + gid;
                if (TB) {
                    b[nj][0] = __float_as_uint(Bs[buf][cb * PA + kk + tig]);
                    b[nj][1] = __float_as_uint(Bs[buf][cb * PA + kk + tig + 4]);
                } else {
                    b[nj][0] = __float_as_uint(Bs[buf][(kk + tig)     * PB + cb]);
                    b[nj][1] = __float_as_uint(Bs[buf][(kk + tig + 4) * PB + cb]);
                }
            }
#pragma unroll
            for (int nj = 0; nj < 4; nj++)
                mma_tf32(acc[nj], a, b[nj]);
        }
        if (kt + 1 < NK) {
            cp_wait0(); __syncthreads();
            buf ^= 1;
        }
    }

#pragma unroll
    for (int nj = 0; nj < 4; nj++) {
        int r0 = m0 + wm + gid;
        int c0 = n0 + wn + nj * 8 + 2 * tig;
        C[(long)r0 * ldc + c0]           = acc[nj][0] * alpha;
        C[(long)r0 * ldc + c0 + 1]       = acc[nj][1] * alpha;
        C[(long)(r0 + 8) * ldc + c0]     = acc[nj][2] * alpha;
        C[(long)(r0 + 8) * ldc + c0 + 1] = acc[nj][3] * alpha;
    }
}

// ---------------------------------------------------------------------------
// Stage 1: Ep = E_flat @ We  (2048x512)  and  Mp = M_flat @ Wm * scale
// (1024x512) in ONE launch. grid = (8, 48): y<32 -> Ep rows, y>=32 -> Mp.
// ---------------------------------------------------------------------------
__global__ __launch_bounds__(256) void k_stage1(
    const float* __restrict__ E, const float* __restrict__ M,
    const float* __restrict__ We, const float* __restrict__ Wm,
    float* __restrict__ Ep, float* __restrict__ Mp, float scale)
{
    __shared__ float As[2][64 * PA];
    __shared__ float Bs[2][2304];

    int by = blockIdx.y, n0 = blockIdx.x * 64;
    if (by < 32)
        gemm_core<false>(E, We, Ep, HD, HD, HD, by * 64, n0, 0, HD, 1.f,
                         As, Bs);
    else
        gemm_core<false>(M, Wm, Mp, HD, HD, HD, (by - 32) * 64, n0, 0, HD,
                         scale, As, Bs);
}

// ---------------------------------------------------------------------------
// Stage 2: partial logits[b] = Mp[b] @ Ep[b]^T over half the K range.
// grid = (8, 4, 8): z = b*2 + h; h selects K half and partial buffer.
// ---------------------------------------------------------------------------
__global__ __launch_bounds__(256) void k_stage2(
    const float* __restrict__ Mp, const float* __restrict__ Ep,
    float* __restrict__ logA, float* __restrict__ logB)
{
    __shared__ float As[2][64 * PA];
    __shared__ float Bs[2][2304];

    int z = blockIdx.z;
    int b = z >> 1, h = z & 1;
    const float* A = Mp + (long)b * LM * HD;
    const float* B = Ep + (long)b * LE * HD;
    float* C = (h ? logB : logA) + (long)b * LM * LE;
    gemm_core<true>(A, B, C, HD, HD, LE, blockIdx.y * 64, blockIdx.x * 64,
                    h * 256, 256, 1.f, As, Bs);
}

// ---------------------------------------------------------------------------
// One block per (b,m) row: dual softmax over logA+logB (with the two bias
// vectors), combine with lambda, scatter-add at inputs[b,e].
// Output rows pre-zeroed by k_zero (ordered via the graph join).
// ---------------------------------------------------------------------------
__global__ __launch_bounds__(256) void k_scatter(
    const int* __restrict__ idx, const float* __restrict__ bq,
    const float* __restrict__ bc, float* __restrict__ out)
{
    int r = blockIdx.x;
    int b = r / LM;
    int t = threadIdx.x;

    float* orow = out + (long)r * VOC;
    const float* la = g_logA + (long)r * LE;
    const float* lb = g_logB + (long)r * LE;
    float lam = g_lam[r];

    float vq[2], vc[2];
#pragma unroll
    for (int i = 0; i < 2; i++) {
        int e = t + i * 256;
        float l = la[e] + lb[e];
        vq[i] = l + bq[b * LE + e];
        vc[i] = l + bc[b * LE + e];
    }

    __shared__ float red[256];
    red[t] = fmaxf(vq[0], vq[1]); __syncthreads();
    for (int o = 128; o > 0; o >>= 1) {
        if (t < o) red[t] = fmaxf(red[t], red[t + o]);
        __syncthreads();
    }
    float mq = red[0]; __syncthreads();
    red[t] = fmaxf(vc[0], vc[1]); __syncthreads();
    for (int o = 128; o > 0; o >>= 1) {
        if (t < o) red[t] = fmaxf(red[t], red[t + o]);
        __syncthreads();
    }
    float mc = red[0]; __syncthreads();

    float eq[2], ec[2], sq = 0.f, sc = 0.f;
#pragma unroll
    for (int i = 0; i < 2; i++) {
        eq[i] = __expf(vq[i] - mq); sq += eq[i];
        ec[i] = __expf(vc[i] - mc); sc += ec[i];
    }
    red[t] = sq; __syncthreads();
    for (int o = 128; o > 0; o >>= 1) {
        if (t < o) red[t] += red[t + o];
        __syncthreads();
    }
    sq = red[0]; __syncthreads();
    red[t] = sc; __syncthreads();
    for (int o = 128; o > 0; o >>= 1) {
        if (t < o) red[t] += red[t + o];
        __syncthreads();
    }
    sc = red[0];

    float iq = lam / sq, ic = (1.f - lam) / sc;
#pragma unroll
    for (int i = 0; i < 2; i++) {
        int e = t + i * 256;
        atomicAdd(orow + idx[b * LE + e], eq[i] * iq + ec[i] * ic);
    }
}

// ---------------------------------------------------------------------------
extern "C" void kernel_launch(void* const* d_in, const int* in_sizes, int n_in,
                              void* d_out, int out_size)
{
    const int*   inputs = (const int*)  d_in[0];
    const float* D      = (const float*)d_in[1];
    const float* Cq     = (const float*)d_in[2];
    const float* Cc     = (const float*)d_in[3];
    const float* Mi     = (const float*)d_in[4];
    const float* E      = (const float*)d_in[5];
    const float* bq     = (const float*)d_in[6];
    const float* bc     = (const float*)d_in[7];
    const float* Wl     = (const float*)d_in[8];
    const float* bl     = (const float*)d_in[9];
    const float* We     = (const float*)d_in[10];
    const float* Wm     = (const float*)d_in[11];
    float* out = (float*)d_out;

    float *gEp, *gMp, *gLA, *gLB;
    cudaGetSymbolAddress((void**)&gEp, g_Ep);
    cudaGetSymbolAddress((void**)&gMp, g_Mp);
    cudaGetSymbolAddress((void**)&gLA, g_logA);
    cudaGetSymbolAddress((void**)&gLB, g_logB);

    static cudaStream_t s2 = nullptr;
    static cudaEvent_t evFork = nullptr, evJoin = nullptr;
    if (s2 == nullptr) {
        cudaStreamCreateWithFlags(&s2, cudaStreamNonBlocking);
        cudaEventCreateWithFlags(&evFork, cudaEventDisableTiming);
        cudaEventCreateWithFlags(&evJoin, cudaEventDisableTiming);
    }

    const float scale = 0.044194173824159216f;  // 512^-0.5
    const long n4 = (long)BSZ * LM * VOC / 4;   // 8,192,000 float4

    // ---- fork: side branch computes lambda + zeroes the output -------------
    cudaEventRecord(evFork, 0);
    cudaStreamWaitEvent(s2, evFork, 0);
    k_lambda<<<128, 256, 0, s2>>>(D, Cq, Cc, Wl, bl);
    k_zero<<<296, 256, 0, s2>>>((float4*)out, n4);
    cudaEventRecord(evJoin, s2);

    // ---- main branch: 2-stage GEMM chain -----------------------------------
    k_stage1<<<dim3(8, 48, 1), 256>>>(E, Mi, We, Wm, gEp, gMp, scale);
    k_stage2<<<dim3(8, 4, 8), 256>>>(gMp, gEp, gLA, gLB);

    // ---- join + scatter ----------------------------------------------------
    cudaStreamWaitEvent(0, evJoin, 0);
    k_scatter<<<BSZ * LM, 256>>>(inputs, bq, bc, out);
}

// round 7
// speedup vs baseline: 1.4839x; 1.2944x over previous
#include <cuda_runtime.h>
#include <cstdint>

#define BSZ 4
#define LM  256
#define LE  512
#define HD  512
#define VOC 32000
#define HALF (VOC / 2)   // 16000 floats = 64 KB smem per scatter block

// Scratch (device globals; no allocation allowed in kernel_launch)
__device__ float g_Ep[BSZ * LE * HD];        // E @ We               (4 MB)
__device__ float g_Mp[BSZ * LM * HD];        // M @ Wm * scale       (2 MB)
__device__ float g_log[4][BSZ * LM * LE];    // logits K-split partials (8 MB)

// ---------------------------------------------------------------------------
// tf32 tensor-core GEMM core: 64x64 tile, 256 threads (4x2 warps of 16x32),
// BK=32, cp.async double-buffered smem, mma.sync.m16n8k8.tf32.
// TB=true:  C[m,n] = alpha * sum_k A[m,k] * B[n,k]   (NT, both K-major)
// TB=false: C[m,n] = alpha * sum_k A[m,k] * B[k,n]   (NN)
// ---------------------------------------------------------------------------
__device__ __forceinline__ void cp16(void* dst, const void* src)
{
    uint32_t d = (uint32_t)__cvta_generic_to_shared(dst);
    asm volatile("cp.async.cg.shared.global [%0], [%1], 16;\n"
                 :: "r"(d), "l"(src));
}
__device__ __forceinline__ void cp_commit()
{
    asm volatile("cp.async.commit_group;\n" ::: "memory");
}
__device__ __forceinline__ void cp_wait0()
{
    asm volatile("cp.async.wait_group 0;\n" ::: "memory");
}
__device__ __forceinline__ void mma_tf32(float* d, const uint32_t* a,
                                         const uint32_t* b)
{
    asm volatile(
        "mma.sync.aligned.m16n8k8.row.col.f32.tf32.tf32.f32 "
        "{%0,%1,%2,%3}, {%4,%5,%6,%7}, {%8,%9}, {%0,%1,%2,%3};\n"
        : "+f"(d[0]), "+f"(d[1]), "+f"(d[2]), "+f"(d[3])
        : "r"(a[0]), "r"(a[1]), "r"(a[2]), "r"(a[3]),
          "r"(b[0]), "r"(b[1]));
}

#define PA 36   // smem pitch, K-major tiles (banks 4*gid+tig: conflict-free)
#define PB 72   // smem pitch, NN B tile     (banks 8*tig+gid: conflict-free)

template <bool TB>
__device__ __forceinline__ void gemm_core(
    const float* __restrict__ A, const float* __restrict__ B,
    float* __restrict__ C, int lda, int ldb, int ldc,
    int m0, int n0, int kOff, int kLen, float alpha,
    float (&As)[2][64 * PA], float (&Bs)[2][2304])
{
    const int tid  = threadIdx.x;
    const int lane = tid & 31, w = tid >> 5;
    const int gid = lane >> 2, tig = lane & 3;
    const int wm = (w & 3) * 16, wn = (w >> 2) * 32;

    const int NK = kLen / 32;

    auto loadA = [&](int buf, int kt) {
        int k0 = kOff + kt * 32;
#pragma unroll
        for (int i = 0; i < 2; i++) {
            int id = tid + i * 256;
            int row = id >> 3, cc = id & 7;
            cp16(&As[buf][row * PA + cc * 4],
                 A + (long)(m0 + row) * lda + k0 + cc * 4);
        }
    };
    auto loadB = [&](int buf, int kt) {
        int k0 = kOff + kt * 32;
        if (TB) {
#pragma unroll
            for (int i = 0; i < 2; i++) {
                int id = tid + i * 256;
                int row = id >> 3, cc = id & 7;
                cp16(&Bs[buf][row * PA + cc * 4],
                     B + (long)(n0 + row) * ldb + k0 + cc * 4);
            }
        } else {
#pragma unroll
            for (int i = 0; i < 2; i++) {
                int id = tid + i * 256;
                int row = id >> 4, cc = id & 15;
                cp16(&Bs[buf][row * PB + cc * 4],
                     B + (long)(k0 + row) * ldb + n0 + cc * 4);
            }
        }
    };

    float acc[4][4] = {};

    loadA(0, 0); loadB(0, 0); cp_commit();
    cp_wait0(); __syncthreads();

    int buf = 0;
    for (int kt = 0; kt < NK; kt++) {
        if (kt + 1 < NK) {
            loadA(buf ^ 1, kt + 1);
            loadB(buf ^ 1, kt + 1);
            cp_commit();
        }
#pragma unroll
        for (int ks = 0; ks < 4; ks++) {
            const int kk = ks * 8;
            uint32_t a[4];
            {
                int rb = wm + gid;
                a[0] = __float_as_uint(As[buf][(rb)     * PA + kk + tig]);
                a[1] = __float_as_uint(As[buf][(rb + 8) * PA + kk + tig]);
                a[2] = __float_as_uint(As[buf][(rb)     * PA + kk + tig + 4]);
                a[3] = __float_as_uint(As[buf][(rb + 8) * PA + kk + tig + 4]);
            }
            uint32_t b[4][2];
#pragma unroll
            for (int nj = 0; nj < 4; nj++) {
                int cb = wn + nj * 8 + gid;
                if (TB) {
                    b[nj][0] = __float_as_uint(Bs[buf][cb * PA + kk + tig]);
                    b[nj][1] = __float_as_uint(Bs[buf][cb * PA + kk + tig + 4]);
                } else {
                    b[nj][0] = __float_as_uint(Bs[buf][(kk + tig)     * PB + cb]);
                    b[nj][1] = __float_as_uint(Bs[buf][(kk + tig + 4) * PB + cb]);
                }
            }
#pragma unroll
            for (int nj = 0; nj < 4; nj++)
                mma_tf32(acc[nj], a, b[nj]);
        }
        if (kt + 1 < NK) {
            cp_wait0(); __syncthreads();
            buf ^= 1;
        }
    }

#pragma unroll
    for (int nj = 0; nj < 4; nj++) {
        int r0 = m0 + wm + gid;
        int c0 = n0 + wn + nj * 8 + 2 * tig;
        C[(long)r0 * ldc + c0]           = acc[nj][0] * alpha;
        C[(long)r0 * ldc + c0 + 1]       = acc[nj][1] * alpha;
        C[(long)(r0 + 8) * ldc + c0]     = acc[nj][2] * alpha;
        C[(long)(r0 + 8) * ldc + c0 + 1] = acc[nj][3] * alpha;
    }
}

// ---------------------------------------------------------------------------
// Stage 1: Ep = E_flat @ We  (2048x512)  and  Mp = M_flat @ Wm * scale
// (1024x512) in ONE launch. grid = (8, 48): y<32 -> Ep rows, y>=32 -> Mp.
// ---------------------------------------------------------------------------
__global__ __launch_bounds__(256) void k_stage1(
    const float* __restrict__ E, const float* __restrict__ M,
    const float* __restrict__ We, const float* __restrict__ Wm,
    float* __restrict__ Ep, float* __restrict__ Mp, float scale)
{
    __shared__ float As[2][64 * PA];
    __shared__ float Bs[2][2304];

    int by = blockIdx.y, n0 = blockIdx.x * 64;
    if (by < 32)
        gemm_core<false>(E, We, Ep, HD, HD, HD, by * 64, n0, 0, HD, 1.f,
                         As, Bs);
    else
        gemm_core<false>(M, Wm, Mp, HD, HD, HD, (by - 32) * 64, n0, 0, HD,
                         scale, As, Bs);
}

// ---------------------------------------------------------------------------
// Stage 2: partial logits[b] = Mp[b] @ Ep[b]^T over a quarter of the K range.
// grid = (8, 4, 16): z = b*4 + h; h selects K quarter and partial buffer.
// ---------------------------------------------------------------------------
__global__ __launch_bounds__(256) void k_stage2(
    const float* __restrict__ Mp, const float* __restrict__ Ep,
    float* __restrict__ logs)
{
    __shared__ float As[2][64 * PA];
    __shared__ float Bs[2][2304];

    int z = blockIdx.z;
    int b = z >> 2, h = z & 3;
    const float* A = Mp + (long)b * LM * HD;
    const float* B = Ep + (long)b * LE * HD;
    float* C = logs + (long)h * BSZ * LM * LE + (long)b * LM * LE;
    gemm_core<true>(A, B, C, HD, HD, LE, blockIdx.y * 64, blockIdx.x * 64,
                    h * 128, 128, 1.f, As, Bs);
}

// ---------------------------------------------------------------------------
// Block reduction for 512 threads (16 warps). red16 is a 16-float smem array.
// ---------------------------------------------------------------------------
__device__ __forceinline__ float bred512(float v, bool mx, float* red16,
                                         int lane, int w)
{
#pragma unroll
    for (int o = 16; o > 0; o >>= 1) {
        float u = __shfl_xor_sync(0xffffffffu, v, o);
        v = mx ? fmaxf(v, u) : v + u;
    }
    if (lane == 0) red16[w] = v;
    __syncthreads();
    float x = red16[lane & 15];
#pragma unroll
    for (int o = 8; o > 0; o >>= 1) {
        float u = __shfl_xor_sync(0xffffffffu, x, o);
        x = mx ? fmaxf(x, u) : x + u;
    }
    __syncthreads();   // red16 free for next use
    return x;          // identical in every thread
}

// ---------------------------------------------------------------------------
// Fused output kernel. grid = (2 vocab halves, 1024 rows), 512 threads,
// 64 KB dynamic smem (half an output row). Per block:
//   zero smem half-row; compute lambda inline; sum K-split logit partials;
//   dual softmax; scatter-add into smem; stream the half-row to GMEM (__stcs).
// No pre-zero pass and no global atomics: output is written exactly once.
// ---------------------------------------------------------------------------
__global__ __launch_bounds__(512) void k_scatter(
    const int* __restrict__ idx, const float* __restrict__ bq,
    const float* __restrict__ bc, const float* __restrict__ D,
    const float* __restrict__ Cq, const float* __restrict__ Cc,
    const float* __restrict__ Wl, const float* __restrict__ bl,
    const float* __restrict__ logs, float* __restrict__ out)
{
    extern __shared__ float vrow[];          // HALF floats (64 KB)
    __shared__ float red16[16];

    const int r = blockIdx.y;                // 0 .. BSZ*LM-1
    const int h = blockIdx.x;                // vocab half
    const int b = r >> 8;                    // r / LM
    const int t = threadIdx.x, lane = t & 31, w = t >> 5;

    // zero the smem half-row
    float4* v4 = (float4*)vrow;
    for (int i = t; i < HALF / 4; i += 512)
        v4[i] = make_float4(0.f, 0.f, 0.f, 0.f);

    // lambda (512 threads x 1 element each of the 3 concatenated chunks)
    const float* dr  = D  + (long)r * HD;
    const float* cqr = Cq + (long)r * HD;
    const float* ccr = Cc + (long)r * HD;
    float s = dr[t] * Wl[t] + cqr[t] * Wl[HD + t] + ccr[t] * Wl[2 * HD + t];
    s = bred512(s, false, red16, lane, w);
    float lam = 1.f / (1.f + __expf(-(s + bl[0])));

    // logits: one element per thread (LE == 512)
    const long rl = (long)r * LE + t;
    const long str = (long)BSZ * LM * LE;
    float l = logs[rl] + logs[str + rl] + logs[2 * str + rl] + logs[3 * str + rl];
    float vq = l + bq[b * LE + t];
    float vc = l + bc[b * LE + t];

    float mq = bred512(vq, true, red16, lane, w);
    float mc = bred512(vc, true, red16, lane, w);
    float eq = __expf(vq - mq);
    float ec = __expf(vc - mc);
    float sq = bred512(eq, false, red16, lane, w);
    float sc = bred512(ec, false, red16, lane, w);

    float wgt = lam * eq / sq + (1.f - lam) * ec / sc;
    int ix = idx[b * LE + t] - h * HALF;
    if (ix >= 0 && ix < HALF)
        atomicAdd(&vrow[ix], wgt);
    __syncthreads();

    // stream the half-row out (write-once; no pre-zero needed)
    float4* orow4 = (float4*)(out + (long)r * VOC + (long)h * HALF);
    for (int i = t; i < HALF / 4; i += 512)
        __stcs(orow4 + i, v4[i]);
}

// ---------------------------------------------------------------------------
extern "C" void kernel_launch(void* const* d_in, const int* in_sizes, int n_in,
                              void* d_out, int out_size)
{
    const int*   inputs = (const int*)  d_in[0];
    const float* D      = (const float*)d_in[1];
    const float* Cq     = (const float*)d_in[2];
    const float* Cc     = (const float*)d_in[3];
    const float* Mi     = (const float*)d_in[4];
    const float* E      = (const float*)d_in[5];
    const float* bq     = (const float*)d_in[6];
    const float* bc     = (const float*)d_in[7];
    const float* Wl     = (const float*)d_in[8];
    const float* bl     = (const float*)d_in[9];
    const float* We     = (const float*)d_in[10];
    const float* Wm     = (const float*)d_in[11];
    float* out = (float*)d_out;

    float *gEp, *gMp, *gL;
    cudaGetSymbolAddress((void**)&gEp, g_Ep);
    cudaGetSymbolAddress((void**)&gMp, g_Mp);
    cudaGetSymbolAddress((void**)&gL,  g_log);

    static bool init = false;
    if (!init) {
        cudaFuncSetAttribute(k_scatter,
                             cudaFuncAttributeMaxDynamicSharedMemorySize,
                             HALF * sizeof(float));
        init = true;
    }

    const float scale = 0.044194173824159216f;  // 512^-0.5

    // Ep = E @ We, Mp = M @ Wm * scale   (one wide launch, 384 blocks)
    k_stage1<<<dim3(8, 48, 1), 256>>>(E, Mi, We, Wm, gEp, gMp, scale);
    // logits partials, K-split 4        (512 blocks)
    k_stage2<<<dim3(8, 4, 16), 256>>>(gMp, gEp, gL);
    // fused lambda + softmax + scatter + streamed row write (2048 blocks)
    k_scatter<<<dim3(2, BSZ * LM), 512, HALF * sizeof(float)>>>(
        inputs, bq, bc, D, Cq, Cc, Wl, bl, gL, out);
}

// round 8
// speedup vs baseline: 1.5862x; 1.0690x over previous
#include <cuda_runtime.h>
#include <cstdint>

#define BSZ 4
#define LM  256
#define LE  512
#define HD  512
#define VOC 32000
#define HALF (VOC / 2)   // 16000 floats = 64 KB smem per scatter block

// Scratch (device globals; no allocation allowed in kernel_launch)
__device__ float g_G[HD * HD];               // Wm @ We^T * scale    (1 MB)
__device__ float g_T[BSZ * LM * HD];         // M @ G                (2 MB)
__device__ float g_log[4][BSZ * LM * LE];    // logits K-split partials (8 MB)

// ---------------------------------------------------------------------------
// Zero the atomic accumulators (G and T). Tiny (3 MB).
// ---------------------------------------------------------------------------
__global__ __launch_bounds__(256) void k_zero(
    float4* __restrict__ a, long na4, float4* __restrict__ b, long nb4)
{
    long i = (long)blockIdx.x * blockDim.x + threadIdx.x;
    long s = (long)gridDim.x * blockDim.x;
    float4 z = make_float4(0.f, 0.f, 0.f, 0.f);
    for (long j = i; j < na4; j += s) a[j] = z;
    for (long j = i; j < nb4; j += s) b[j] = z;
}

// ---------------------------------------------------------------------------
// tf32 tensor-core GEMM core: 64x64 tile, 256 threads (4x2 warps of 16x32),
// BK=32, cp.async double-buffered smem, mma.sync.m16n8k8.tf32.
// TB=true:  C[m,n] (+)= alpha * sum_k A[m,k] * B[n,k]   (NT, both K-major)
// TB=false: C[m,n] (+)= alpha * sum_k A[m,k] * B[k,n]   (NN)
// ATOMIC=true: accumulate into C with atomicAdd (for K-split partial sums).
// ---------------------------------------------------------------------------
__device__ __forceinline__ void cp16(void* dst, const void* src)
{
    uint32_t d = (uint32_t)__cvta_generic_to_shared(dst);
    asm volatile("cp.async.cg.shared.global [%0], [%1], 16;\n"
                 :: "r"(d), "l"(src));
}
__device__ __forceinline__ void cp_commit()
{
    asm volatile("cp.async.commit_group;\n" ::: "memory");
}
__device__ __forceinline__ void cp_wait0()
{
    asm volatile("cp.async.wait_group 0;\n" ::: "memory");
}
__device__ __forceinline__ void mma_tf32(float* d, const uint32_t* a,
                                         const uint32_t* b)
{
    asm volatile(
        "mma.sync.aligned.m16n8k8.row.col.f32.tf32.tf32.f32 "
        "{%0,%1,%2,%3}, {%4,%5,%6,%7}, {%8,%9}, {%0,%1,%2,%3};\n"
        : "+f"(d[0]), "+f"(d[1]), "+f"(d[2]), "+f"(d[3])
        : "r"(a[0]), "r"(a[1]), "r"(a[2]), "r"(a[3]),
          "r"(b[0]), "r"(b[1]));
}

#define PA 36   // smem pitch, K-major tiles (banks 4*gid+tig: conflict-free)
#define PB 72   // smem pitch, NN B tile     (banks 8*tig+gid: conflict-free)

template <bool TB, bool ATOMIC>
__device__ __forceinline__ void gemm_core(
    const float* __restrict__ A, const float* __restrict__ B,
    float* __restrict__ C, int lda, int ldb, int ldc,
    int m0, int n0, int kOff, int kLen, float alpha,
    float (&As)[2][64 * PA], float (&Bs)[2][2304])
{
    const int tid  = threadIdx.x;
    const int lane = tid & 31, w = tid >> 5;
    const int gid = lane >> 2, tig = lane & 3;
    const int wm = (w & 3) * 16, wn = (w >> 2) * 32;

    const int NK = kLen / 32;

    auto loadA = [&](int buf, int kt) {
        int k0 = kOff + kt * 32;
#pragma unroll
        for (int i = 0; i < 2; i++) {
            int id = tid + i * 256;
            int row = id >> 3, cc = id & 7;
            cp16(&As[buf][row * PA + cc * 4],
                 A + (long)(m0 + row) * lda + k0 + cc * 4);
        }
    };
    auto loadB = [&](int buf, int kt) {
        int k0 = kOff + kt * 32;
        if (TB) {
#pragma unroll
            for (int i = 0; i < 2; i++) {
                int id = tid + i * 256;
                int row = id >> 3, cc = id & 7;
                cp16(&Bs[buf][row * PA + cc * 4],
                     B + (long)(n0 + row) * ldb + k0 + cc * 4);
            }
        } else {
#pragma unroll
            for (int i = 0; i < 2; i++) {
                int id = tid + i * 256;
                int row = id >> 4, cc = id & 15;
                cp16(&Bs[buf][row * PB + cc * 4],
                     B + (long)(k0 + row) * ldb + n0 + cc * 4);
            }
        }
    };

    float acc[4][4] = {};

    loadA(0, 0); loadB(0, 0); cp_commit();
    cp_wait0(); __syncthreads();

    int buf = 0;
    for (int kt = 0; kt < NK; kt++) {
        if (kt + 1 < NK) {
            loadA(buf ^ 1, kt + 1);
            loadB(buf ^ 1, kt + 1);
            cp_commit();
        }
#pragma unroll
        for (int ks = 0; ks < 4; ks++) {
            const int kk = ks * 8;
            uint32_t a[4];
            {
                int rb = wm + gid;
                a[0] = __float_as_uint(As[buf][(rb)     * PA + kk + tig]);
                a[1] = __float_as_uint(As[buf][(rb + 8) * PA + kk + tig]);
                a[2] = __float_as_uint(As[buf][(rb)     * PA + kk + tig + 4]);
                a[3] = __float_as_uint(As[buf][(rb + 8) * PA + kk + tig + 4]);
            }
            uint32_t b[4][2];
#pragma unroll
            for (int nj = 0; nj < 4; nj++) {
                int cb = wn + nj * 8 + gid;
                if (TB) {
                    b[nj][0] = __float_as_uint(Bs[buf][cb * PA + kk + tig]);
                    b[nj][1] = __float_as_uint(Bs[buf][cb * PA + kk + tig + 4]);
                } else {
                    b[nj][0] = __float_as_uint(Bs[buf][(kk + tig)     * PB + cb]);
                    b[nj][1] = __float_as_uint(Bs[buf][(kk + tig + 4) * PB + cb]);
                }
            }
#pragma unroll
            for (int nj = 0; nj < 4; nj++)
                mma_tf32(acc[nj], a, b[nj]);
        }
        if (kt + 1 < NK) {
            cp_wait0(); __syncthreads();
            buf ^= 1;
        }
    }

#pragma unroll
    for (int nj = 0; nj < 4; nj++) {
        int r0 = m0 + wm + gid;
        int c0 = n0 + wn + nj * 8 + 2 * tig;
        if (ATOMIC) {
            atomicAdd(&C[(long)r0 * ldc + c0],           acc[nj][0] * alpha);
            atomicAdd(&C[(long)r0 * ldc + c0 + 1],       acc[nj][1] * alpha);
            atomicAdd(&C[(long)(r0 + 8) * ldc + c0],     acc[nj][2] * alpha);
            atomicAdd(&C[(long)(r0 + 8) * ldc + c0 + 1], acc[nj][3] * alpha);
        } else {
            C[(long)r0 * ldc + c0]           = acc[nj][0] * alpha;
            C[(long)r0 * ldc + c0 + 1]       = acc[nj][1] * alpha;
            C[(long)(r0 + 8) * ldc + c0]     = acc[nj][2] * alpha;
            C[(long)(r0 + 8) * ldc + c0 + 1] = acc[nj][3] * alpha;
        }
    }
}

// ---------------------------------------------------------------------------
// G = Wm @ We^T * scale  (512x512, NT), K-split x4 with atomic accumulation.
// grid = (8, 8, 4) = 256 blocks.
// ---------------------------------------------------------------------------
__global__ __launch_bounds__(256) void k_G(
    const float* __restrict__ Wm, const float* __restrict__ We,
    float* __restrict__ G, float scale)
{
    __shared__ float As[2][64 * PA];
    __shared__ float Bs[2][2304];
    gemm_core<true, true>(Wm, We, G, HD, HD, HD,
                          blockIdx.y * 64, blockIdx.x * 64,
                          blockIdx.z * 128, 128, scale, As, Bs);
}

// ---------------------------------------------------------------------------
// T = M_flat @ G  (1024x512, NN), K-split x2 with atomic accumulation.
// grid = (8, 16, 2) = 256 blocks.
// ---------------------------------------------------------------------------
__global__ __launch_bounds__(256) void k_T(
    const float* __restrict__ M, const float* __restrict__ G,
    float* __restrict__ T)
{
    __shared__ float As[2][64 * PA];
    __shared__ float Bs[2][2304];
    gemm_core<false, true>(M, G, T, HD, HD, HD,
                           blockIdx.y * 64, blockIdx.x * 64,
                           blockIdx.z * 256, 256, 1.f, As, Bs);
}

// ---------------------------------------------------------------------------
// logits[b] = T[b] @ E[b]^T (NT), K-split x4 into 4 separate partial buffers.
// grid = (8, 4, 16): z = b*4 + h.
// ---------------------------------------------------------------------------
__global__ __launch_bounds__(256) void k_log(
    const float* __restrict__ T, const float* __restrict__ E,
    float* __restrict__ logs)
{
    __shared__ float As[2][64 * PA];
    __shared__ float Bs[2][2304];

    int z = blockIdx.z;
    int b = z >> 2, h = z & 3;
    const float* A = T + (long)b * LM * HD;
    const float* B = E + (long)b * LE * HD;
    float* C = logs + (long)h * BSZ * LM * LE + (long)b * LM * LE;
    gemm_core<true, false>(A, B, C, HD, HD, LE,
                           blockIdx.y * 64, blockIdx.x * 64,
                           h * 128, 128, 1.f, As, Bs);
}

// ---------------------------------------------------------------------------
// Block reduction for 512 threads (16 warps). red16 is a 16-float smem array.
// ---------------------------------------------------------------------------
__device__ __forceinline__ float bred512(float v, bool mx, float* red16,
                                         int lane, int w)
{
#pragma unroll
    for (int o = 16; o > 0; o >>= 1) {
        float u = __shfl_xor_sync(0xffffffffu, v, o);
        v = mx ? fmaxf(v, u) : v + u;
    }
    if (lane == 0) red16[w] = v;
    __syncthreads();
    float x = red16[lane & 15];
#pragma unroll
    for (int o = 8; o > 0; o >>= 1) {
        float u = __shfl_xor_sync(0xffffffffu, x, o);
        x = mx ? fmaxf(x, u) : x + u;
    }
    __syncthreads();   // red16 free for next use
    return x;          // identical in every thread
}

// ---------------------------------------------------------------------------
// Fused output kernel. grid = (2 vocab halves, 1024 rows), 512 threads,
// 64 KB dynamic smem (half an output row). Per block:
//   zero smem half-row; compute lambda inline; sum K-split logit partials;
//   dual softmax; scatter-add into smem; stream the half-row to GMEM (__stcs).
// No pre-zero pass and no global atomics: output is written exactly once.
// ---------------------------------------------------------------------------
__global__ __launch_bounds__(512) void k_scatter(
    const int* __restrict__ idx, const float* __restrict__ bq,
    const float* __restrict__ bc, const float* __restrict__ D,
    const float* __restrict__ Cq, const float* __restrict__ Cc,
    const float* __restrict__ Wl, const float* __restrict__ bl,
    const float* __restrict__ logs, float* __restrict__ out)
{
    extern __shared__ float vrow[];          // HALF floats (64 KB)
    __shared__ float red16[16];

    const int r = blockIdx.y;                // 0 .. BSZ*LM-1
    const int h = blockIdx.x;                // vocab half
    const int b = r >> 8;                    // r / LM
    const int t = threadIdx.x, lane = t & 31, w = t >> 5;

    // zero the smem half-row
    float4* v4 = (float4*)vrow;
    for (int i = t; i < HALF / 4; i += 512)
        v4[i] = make_float4(0.f, 0.f, 0.f, 0.f);

    // lambda (512 threads x 1 element each of the 3 concatenated chunks)
    const float* dr  = D  + (long)r * HD;
    const float* cqr = Cq + (long)r * HD;
    const float* ccr = Cc + (long)r * HD;
    float s = dr[t] * Wl[t] + cqr[t] * Wl[HD + t] + ccr[t] * Wl[2 * HD + t];
    s = bred512(s, false, red16, lane, w);
    float lam = 1.f / (1.f + __expf(-(s + bl[0])));

    // logits: one element per thread (LE == 512), sum of 4 K-split partials
    const long rl = (long)r * LE + t;
    const long str = (long)BSZ * LM * LE;
    float l = logs[rl] + logs[str + rl] + logs[2 * str + rl] + logs[3 * str + rl];
    float vq = l + bq[b * LE + t];
    float vc = l + bc[b * LE + t];

    float mq = bred512(vq, true, red16, lane, w);
    float mc = bred512(vc, true, red16, lane, w);
    float eq = __expf(vq - mq);
    float ec = __expf(vc - mc);
    float sq = bred512(eq, false, red16, lane, w);
    float sc = bred512(ec, false, red16, lane, w);

    float wgt = lam * eq / sq + (1.f - lam) * ec / sc;
    int ix = idx[b * LE + t] - h * HALF;
    if (ix >= 0 && ix < HALF)
        atomicAdd(&vrow[ix], wgt);
    __syncthreads();

    // stream the half-row out (write-once; no pre-zero needed)
    float4* orow4 = (float4*)(out + (long)r * VOC + (long)h * HALF);
    for (int i = t; i < HALF / 4; i += 512)
        __stcs(orow4 + i, v4[i]);
}

// ---------------------------------------------------------------------------
extern "C" void kernel_launch(void* const* d_in, const int* in_sizes, int n_in,
                              void* d_out, int out_size)
{
    const int*   inputs = (const int*)  d_in[0];
    const float* D      = (const float*)d_in[1];
    const float* Cq     = (const float*)d_in[2];
    const float* Cc     = (const float*)d_in[3];
    const float* Mi     = (const float*)d_in[4];
    const float* E      = (const float*)d_in[5];
    const float* bq     = (const float*)d_in[6];
    const float* bc     = (const float*)d_in[7];
    const float* Wl     = (const float*)d_in[8];
    const float* bl     = (const float*)d_in[9];
    const float* We     = (const float*)d_in[10];
    const float* Wm     = (const float*)d_in[11];
    float* out = (float*)d_out;

    float *gG, *gT, *gL;
    cudaGetSymbolAddress((void**)&gG, g_G);
    cudaGetSymbolAddress((void**)&gT, g_T);
    cudaGetSymbolAddress((void**)&gL, g_log);

    static bool init = false;
    if (!init) {
        cudaFuncSetAttribute(k_scatter,
                             cudaFuncAttributeMaxDynamicSharedMemorySize,
                             HALF * sizeof(float));
        init = true;
    }

    const float scale = 0.044194173824159216f;  // 512^-0.5

    // zero atomic accumulators (G: 1 MB, T: 2 MB)
    k_zero<<<192, 256>>>((float4*)gG, HD * HD / 4,
                         (float4*)gT, (long)BSZ * LM * HD / 4);
    // G = Wm @ We^T * scale   (K-split x4, atomic epilogue, 256 blocks)
    k_G<<<dim3(8, 8, 4), 256>>>(Wm, We, gG, scale);
    // T = M_flat @ G          (K-split x2, atomic epilogue, 256 blocks)
    k_T<<<dim3(8, 16, 2), 256>>>(Mi, gG, gT);
    // logits partials         (K-split x4 into 4 buffers, 512 blocks)
    k_log<<<dim3(8, 4, 16), 256>>>(gT, E, gL);
    // fused lambda + softmax + scatter + streamed row write (2048 blocks)
    k_scatter<<<dim3(2, BSZ * LM), 512, HALF * sizeof(float)>>>(
        inputs, bq, bc, D, Cq, Cc, Wl, bl, gL, out);
}